// round 8
// baseline (speedup 1.0000x reference)
#include <cuda_runtime.h>
#include <cuda_bf16.h>
#include <math.h>

// GaussianMixture: B=8, N=131072, K=4, F=20, 5 EM iters, REG_COVAR=1e-4.
// 8-lane team per point. Lane l: components {2g,2g+1} (g=(l>>2)&1),
// features f ≡ (l&3) mod 4 (5 each). All math packed f32x2 across its 2
// components. ~80 regs -> 6 CTAs/SM (128 thr). M-step fused into next accum.

#define BB 8
#define NPTS 131072
#define KC 4
#define FDIM 20
#define NSL 5
#define CTAS_PER_B 111
#define THREADS 128
#define OCT_PER_CTA (THREADS/8)                   // 16
#define STRIDE (CTAS_PER_B*OCT_PER_CTA)           // 1776
#define NIT_FULL 73                               // 73*1776 = 129648
#define TAILN (NPTS - NIT_FULL*STRIDE)            // 1424
#define LOG2PI 1.8378770664093454f

#define RESP_OFF   0
#define LP_OFF     (BB*NPTS*KC)
#define M_OFF      (2*BB*NPTS*KC)
#define COV_OFF    (M_OFF + BB*KC*FDIM)
#define PRIOR_OFF  (COV_OFF + BB*KC*FDIM*FDIM)

typedef unsigned long long u64;

__device__ __forceinline__ u64 pack2(float lo, float hi) {
    u64 d; asm("mov.b64 %0, {%1,%2};" : "=l"(d) : "f"(lo), "f"(hi)); return d;
}
__device__ __forceinline__ void unpack2(u64 v, float& lo, float& hi) {
    asm("mov.b64 {%0,%1}, %2;" : "=f"(lo), "=f"(hi) : "l"(v));
}
__device__ __forceinline__ u64 fma2(u64 a, u64 b, u64 c) {
    u64 d; asm("fma.rn.f32x2 %0, %1, %2, %3;" : "=l"(d) : "l"(a), "l"(b), "l"(c)); return d;
}
__device__ __forceinline__ u64 mul2(u64 a, u64 b) {
    u64 d; asm("mul.rn.f32x2 %0, %1, %2;" : "=l"(d) : "l"(a), "l"(b)); return d;
}
__device__ __forceinline__ u64 add2(u64 a, u64 b) {
    u64 d; asm("add.rn.f32x2 %0, %1, %2;" : "=l"(d) : "l"(a), "l"(b)); return d;
}
__device__ __forceinline__ u64 shfl_xor64(u64 v, int m) {
    return __shfl_xor_sync(0xffffffffu, v, m);
}

// Double-buffered sums: slot it holds results of iteration it.
// Layout per (it,b): [0,80) Sx  [80,160) S2x  [160,240) S2xx  [240,244) S1  [244,248) S2
__device__ float g_sums[5][BB][256];   // zero at load; gmm_final re-zeroes

// ---------------------------------------------------------------------------
__global__ void __launch_bounds__(THREADS, 6)
gmm_accum(const float* __restrict__ data,
          const float* __restrict__ means,
          const float* __restrict__ covv,
          float* __restrict__ out_resp,
          float* __restrict__ out_lp,
          int it, int write_out)
{
    const int b    = blockIdx.y;
    const int tid  = threadIdx.x;
    const int lane = tid & 31;
    const int fb   = lane & 3;                    // feature phase
    const int g    = (lane >> 2) & 1;             // component-pair: {2g, 2g+1}
    const int oct_g = blockIdx.x * OCT_PER_CTA + (tid >> 3);

    __shared__ float s_acc[256];
    for (int i = tid; i < 256; i += THREADS) s_acc[i] = 0.f;

    // ---- prologue: e-step constants (fused M-step of previous iter) ----
    u64 c1p[NSL], c2p[NSL];
    float Ck0, Ck1;
    {
        float c1s[2][NSL], c2s[2][NSL], ldp[2];
        #pragma unroll
        for (int jj = 0; jj < 2; jj++) {
            const int c = 2*g + jj;
            ldp[jj] = 0.f;
            #pragma unroll
            for (int i = 0; i < NSL; i++) {
                const int f = fb + 4*i;
                float mu, var;
                if (it == 0) {
                    mu  = means[(b*KC + c)*FDIM + f];
                    var = covv [(b*KC + c)*FDIM + f];
                } else {
                    const float* s = g_sums[it-1][b];
                    const float S1c = s[240 + c], S2c = s[244 + c];
                    const float sx   = s[        c*FDIM + f];
                    const float s2x  = s[ 80 +   c*FDIM + f];
                    const float s2xx = s[160 +   c*FDIM + f];
                    mu  = sx / S1c;
                    var = (s2xx - 2.f*mu*s2x + mu*mu*S2c) / S1c;
                    var = fmaxf(var, 1e-4f);
                }
                const float iv = 1.f / var;
                c2s[jj][i] = iv;
                c1s[jj][i] = -2.f*mu*iv;
                ldp[jj] += __logf(var) + iv*mu*mu;
            }
        }
        #pragma unroll
        for (int i = 0; i < NSL; i++) {
            c1p[i] = pack2(c1s[0][i], c1s[1][i]);
            c2p[i] = pack2(c2s[0][i], c2s[1][i]);
        }
        // full logdet over 20 features: reduce across feature phases (xor1,2)
        u64 ld = pack2(ldp[0], ldp[1]);
        ld = add2(ld, shfl_xor64(ld, 1));
        ld = add2(ld, shfl_xor64(ld, 2));
        float l0, l1; unpack2(ld, l0, l1);
        Ck0 = -0.5f*(FDIM*LOG2PI + l0);
        Ck1 = -0.5f*(FDIM*LOG2PI + l1);
    }

    // accumulators: comp-pair packed, my 5 features
    u64 Sx[NSL], S2x[NSL], S2xx[NSL], S1p = 0, S2p = 0;
    #pragma unroll
    for (int i = 0; i < NSL; i++) { Sx[i]=0; S2x[i]=0; S2xx[i]=0; }

    const float* __restrict__ xptr = data + (size_t)b*NPTS*FDIM + fb;
    float* __restrict__ orp = out_resp + (size_t)b*NPTS*KC + 2*g;
    float* __restrict__ olp = out_lp   + (size_t)b*NPTS*KC + 2*g;
    const bool wlane = ((lane & 3) == 0);

    auto body = [&](const float x[NSL], int p) {
        // maha partial over my 5 features, both my comps packed
        u64 m = 0;
        #pragma unroll
        for (int i = 0; i < NSL; i++) {
            const u64 xp  = pack2(x[i], x[i]);
            const u64 xxp = mul2(xp, xp);
            m = fma2(c2p[i], xxp, m);
            m = fma2(c1p[i], xp,  m);
        }
        m = add2(m, shfl_xor64(m, 1));
        m = add2(m, shfl_xor64(m, 2));            // full maha over 20 features
        float a0, a1; unpack2(m, a0, a1);
        const float lp0 = fmaf(-0.5f, a0, Ck0);
        const float lp1 = fmaf(-0.5f, a1, Ck1);
        const float pr0 = __expf(lp0) + 1e-8f;
        const float pr1 = __expf(lp1) + 1e-8f;
        const float loc = pr0 + pr1;
        const float s = loc + __shfl_xor_sync(0xffffffffu, loc, 4);
        const float rinv = __fdividef(1.f, s);
        const float r0 = pr0*rinv, r1 = pr1*rinv;
        const u64 rA  = pack2(r0, r1);
        const u64 r2A = mul2(rA, rA);
        S1p = add2(S1p, rA);
        S2p = add2(S2p, r2A);
        #pragma unroll
        for (int i = 0; i < NSL; i++) {
            const u64 xp  = pack2(x[i], x[i]);
            const u64 xxp = mul2(xp, xp);
            Sx[i]   = fma2(rA,  xp,  Sx[i]);
            S2x[i]  = fma2(r2A, xp,  S2x[i]);
            S2xx[i] = fma2(r2A, xxp, S2xx[i]);
        }
        if (write_out && wlane) {
            *(float2*)(orp + (size_t)p*KC) = make_float2(r0, r1);
            *(float2*)(olp + (size_t)p*KC) = make_float2(lp0, lp1);
        }
    };

    // ---- main loop: depth-1 prefetch, 72 full + 1 full + tail ----
    int p = oct_g;
    float x[NSL], xn[NSL];
    #pragma unroll
    for (int i = 0; i < NSL; i++)
        x[i] = __ldg(xptr + (size_t)p*FDIM + 4*i);

    #pragma unroll 1
    for (int j = 0; j < NIT_FULL-1; j++) {        // j=0..71; prefetch j+1<=72 valid
        const int pn = p + STRIDE;
        #pragma unroll
        for (int i = 0; i < NSL; i++)
            xn[i] = __ldg(xptr + (size_t)pn*FDIM + 4*i);
        body(x, p);
        #pragma unroll
        for (int i = 0; i < NSL; i++) x[i] = xn[i];
        p = pn;
    }
    // last full iter (j=72): prefetch tail, clamped
    const bool tvalid = (oct_g < TAILN);
    {
        const int pt = p + STRIDE;
        const int ptc = tvalid ? pt : 0;
        #pragma unroll
        for (int i = 0; i < NSL; i++)
            xn[i] = __ldg(xptr + (size_t)ptc*FDIM + 4*i);
        body(x, p);
        p = pt;
    }
    // tail iter: octet-uniform validity, zero contributions if OOB
    {
        float xt[NSL];
        #pragma unroll
        for (int i = 0; i < NSL; i++) xt[i] = tvalid ? xn[i] : 0.f;
        u64 m = 0;
        #pragma unroll
        for (int i = 0; i < NSL; i++) {
            const u64 xp  = pack2(xt[i], xt[i]);
            const u64 xxp = mul2(xp, xp);
            m = fma2(c2p[i], xxp, m);
            m = fma2(c1p[i], xp,  m);
        }
        m = add2(m, shfl_xor64(m, 1));
        m = add2(m, shfl_xor64(m, 2));
        float a0, a1; unpack2(m, a0, a1);
        const float lp0 = fmaf(-0.5f, a0, Ck0);
        const float lp1 = fmaf(-0.5f, a1, Ck1);
        const float pr0 = __expf(lp0) + 1e-8f;
        const float pr1 = __expf(lp1) + 1e-8f;
        const float loc = pr0 + pr1;
        const float s = loc + __shfl_xor_sync(0xffffffffu, loc, 4);
        const float rinv = __fdividef(1.f, s);
        float r0 = pr0*rinv, r1 = pr1*rinv;
        if (!tvalid) { r0 = 0.f; r1 = 0.f; }
        const u64 rA  = pack2(r0, r1);
        const u64 r2A = mul2(rA, rA);
        S1p = add2(S1p, rA);
        S2p = add2(S2p, r2A);
        #pragma unroll
        for (int i = 0; i < NSL; i++) {
            const u64 xp  = pack2(xt[i], xt[i]);
            const u64 xxp = mul2(xp, xp);
            Sx[i]   = fma2(rA,  xp,  Sx[i]);
            S2x[i]  = fma2(r2A, xp,  S2x[i]);
            S2xx[i] = fma2(r2A, xxp, S2xx[i]);
        }
        if (write_out && wlane && tvalid) {
            *(float2*)(orp + (size_t)p*KC) = make_float2(r0, r1);
            *(float2*)(olp + (size_t)p*KC) = make_float2(lp0, lp1);
        }
    }

    // ---- cross-octet warp reduce (xor 8,16 keeps lane&7) ----
    #pragma unroll
    for (int off = 8; off < 32; off <<= 1) {
        #pragma unroll
        for (int i = 0; i < NSL; i++) {
            Sx[i]   = add2(Sx[i],   shfl_xor64(Sx[i],   off));
            S2x[i]  = add2(S2x[i],  shfl_xor64(S2x[i],  off));
            S2xx[i] = add2(S2xx[i], shfl_xor64(S2xx[i], off));
        }
        S1p = add2(S1p, shfl_xor64(S1p, off));
        S2p = add2(S2p, shfl_xor64(S2p, off));
    }

    __syncthreads();   // s_acc zero-init complete (done at top)

    if (lane < 8) {    // lane = g*4 + fb mapping preserved
        #pragma unroll
        for (int i = 0; i < NSL; i++) {
            const int f = fb + 4*i;
            float lo, hi;
            unpack2(Sx[i], lo, hi);
            atomicAdd(&s_acc[(2*g  )*FDIM + f], lo);
            atomicAdd(&s_acc[(2*g+1)*FDIM + f], hi);
            unpack2(S2x[i], lo, hi);
            atomicAdd(&s_acc[80 + (2*g  )*FDIM + f], lo);
            atomicAdd(&s_acc[80 + (2*g+1)*FDIM + f], hi);
            unpack2(S2xx[i], lo, hi);
            atomicAdd(&s_acc[160 + (2*g  )*FDIM + f], lo);
            atomicAdd(&s_acc[160 + (2*g+1)*FDIM + f], hi);
        }
        if (fb == 0) {  // lanes 0,4: one copy per comp-pair (others are duplicates)
            float lo, hi;
            unpack2(S1p, lo, hi);
            atomicAdd(&s_acc[240 + 2*g], lo);
            atomicAdd(&s_acc[240 + 2*g+1], hi);
            unpack2(S2p, lo, hi);
            atomicAdd(&s_acc[244 + 2*g], lo);
            atomicAdd(&s_acc[244 + 2*g+1], hi);
        }
    }
    __syncthreads();
    for (int i = tid; i < 248; i += THREADS)
        atomicAdd(&g_sums[it][b][i], s_acc[i]);
}

// ---------------------------------------------------------------------------
__global__ void gmm_final(float* __restrict__ out_m,
                          float* __restrict__ out_cov,
                          float* __restrict__ out_prior)
{
    const int b = blockIdx.x;
    const int k = threadIdx.x >> 5;
    const int lane = threadIdx.x & 31;
    const float* s = g_sums[4][b];

    const float S1 = s[240 + k];
    const float S2 = s[244 + k];
    float mu = 0.f, var = 1.f;
    if (lane < FDIM) {
        const float sx   = s[        k*FDIM + lane];
        const float s2x  = s[ 80 +   k*FDIM + lane];
        const float s2xx = s[160 +   k*FDIM + lane];
        mu  = sx / S1;
        var = (s2xx - 2.f*mu*s2x + mu*mu*S2) / S1;
        var = fmaxf(var, 1e-4f);
        out_m[(b*KC + k)*FDIM + lane] = mu;
    }
    if (lane == 0) out_prior[b*KC + k] = S1;
    #pragma unroll
    for (int i = 0; i < FDIM; i++) {
        const float vi = __shfl_sync(0xffffffffu, var, i);
        if (lane < FDIM)
            out_cov[(((size_t)(b*KC + k))*FDIM + i)*FDIM + lane] =
                (lane == i) ? vi : 0.f;
    }

    __syncthreads();
    for (int itt = 0; itt < 5; itt++)
        for (int i = threadIdx.x; i < 256; i += blockDim.x)
            g_sums[itt][b][i] = 0.f;
}

// ---------------------------------------------------------------------------
extern "C" void kernel_launch(void* const* d_in, const int* in_sizes, int n_in,
                              void* d_out, int out_size)
{
    (void)in_sizes; (void)n_in; (void)out_size;
    const float* data  = (const float*)d_in[0];
    const float* means = (const float*)d_in[1];
    const float* cov   = (const float*)d_in[2];
    float* out = (float*)d_out;

    float* out_resp  = out + RESP_OFF;
    float* out_lp    = out + LP_OFF;
    float* out_m     = out + M_OFF;
    float* out_cov   = out + COV_OFF;
    float* out_prior = out + PRIOR_OFF;

    for (int it = 0; it < 5; it++)
        gmm_accum<<<dim3(CTAS_PER_B, BB), THREADS>>>(
            data, means, cov, out_resp, out_lp, it, (it == 4) ? 1 : 0);
    gmm_final<<<BB, 128>>>(out_m, out_cov, out_prior);
}

// round 10
// speedup vs baseline: 1.4100x; 1.4100x over previous
#include <cuda_runtime.h>
#include <cuda_bf16.h>
#include <cstdint>
#include <math.h>

// GaussianMixture: B=8, N=131072, K=4, F=20, 5 EM iters, REG_COVAR=1e-4.
// R5 math/layout (quad teams, f32x2 packed across components, fused M-step)
// + cp.async SMEM ring buffer (depth 6) to hide DRAM latency.

#define BB 8
#define NPTS 131072
#define KC 4
#define FDIM 20
#define NSL 5
#define CTAS_PER_B 37
#define THREADS 256
#define TEAMS_PER_CTA (THREADS/4)                 // 64
#define TEAM_STRIDE (CTAS_PER_B*TEAMS_PER_CTA)    // 2368
#define DEPTH 6
#define STAGE_F (TEAMS_PER_CTA*FDIM)              // 1280 floats = 5120 B
#define CHUNKS (STAGE_F/4)                        // 320 x 16B
#define LOG2PI 1.8378770664093454f

#define RESP_OFF   0
#define LP_OFF     (BB*NPTS*KC)
#define M_OFF      (2*BB*NPTS*KC)
#define COV_OFF    (M_OFF + BB*KC*FDIM)
#define PRIOR_OFF  (COV_OFF + BB*KC*FDIM*FDIM)

typedef unsigned long long u64;
typedef unsigned int u32;

__device__ __forceinline__ u64 pack2(float lo, float hi) {
    u64 d; asm("mov.b64 %0, {%1,%2};" : "=l"(d) : "f"(lo), "f"(hi)); return d;
}
__device__ __forceinline__ void unpack2(u64 v, float& lo, float& hi) {
    asm("mov.b64 {%0,%1}, %2;" : "=f"(lo), "=f"(hi) : "l"(v));
}
__device__ __forceinline__ u64 fma2(u64 a, u64 b, u64 c) {
    u64 d; asm("fma.rn.f32x2 %0, %1, %2, %3;" : "=l"(d) : "l"(a), "l"(b), "l"(c)); return d;
}
__device__ __forceinline__ u64 mul2(u64 a, u64 b) {
    u64 d; asm("mul.rn.f32x2 %0, %1, %2;" : "=l"(d) : "l"(a), "l"(b)); return d;
}
__device__ __forceinline__ u64 add2(u64 a, u64 b) {
    u64 d; asm("add.rn.f32x2 %0, %1, %2;" : "=l"(d) : "l"(a), "l"(b)); return d;
}
__device__ __forceinline__ u64 shfl_xor64(u64 v, int m) {
    return __shfl_xor_sync(0xffffffffu, v, m);
}
__device__ __forceinline__ void cp16(u32 saddr, const void* gaddr) {
    asm volatile("cp.async.cg.shared.global [%0], [%1], 16;" :: "r"(saddr), "l"(gaddr));
}
__device__ __forceinline__ void cp_commit() {
    asm volatile("cp.async.commit_group;");
}
template<int N> __device__ __forceinline__ void cp_wait() {
    asm volatile("cp.async.wait_group %0;" :: "n"(N));
}

// Double-buffered sums: slot it holds results of iteration it.
__device__ float g_sums[5][BB][256];   // zero at load; gmm_final re-zeroes

struct Consts {
    u64 c1A[NSL], c1B[NSL], c2A[NSL], c2B[NSL];
    float Ck;
};

// ---------------------------------------------------------------------------
__global__ void __launch_bounds__(THREADS, 2)
gmm_accum(const float* __restrict__ data,
          const float* __restrict__ means,
          const float* __restrict__ covv,
          float* __restrict__ out_resp,
          float* __restrict__ out_lp,
          int it, int write_out)
{
    const int b    = blockIdx.y;
    const int tid  = threadIdx.x;
    const int lane = tid & 31;
    const int t    = lane & 3;
    const int tp   = tid >> 2;                     // team within CTA
    const int team_g = blockIdx.x * TEAMS_PER_CTA + tp;
    // per-CTA uniform body count: 131072 = 55*2368 + 832, 832 = 13*64
    const int nbody = (blockIdx.x < 13) ? 56 : 55;

    __shared__ float s_ring[DEPTH][STAGE_F];
    __shared__ float s_acc[256];

    // ---- prologue: fused M-step of previous iteration (constants -> regs) ----
    Consts cst;
    {
        float c1s[KC][NSL], c2s[KC][NSL], ldp[KC];
        #pragma unroll
        for (int jj = 0; jj < KC; jj++) {
            const int c = t ^ jj;
            ldp[jj] = 0.f;
            #pragma unroll
            for (int i = 0; i < NSL; i++) {
                const int f = t + 4*i;
                float mu, var;
                if (it == 0) {
                    mu  = means[(b*KC + c)*FDIM + f];
                    var = covv [(b*KC + c)*FDIM + f];
                } else {
                    const float* s = g_sums[it-1][b];
                    const float S1c = s[240 + c], S2c = s[244 + c];
                    const float sx   = s[        c*FDIM + f];
                    const float s2x  = s[ 80 +   c*FDIM + f];
                    const float s2xx = s[160 +   c*FDIM + f];
                    mu  = sx / S1c;
                    var = (s2xx - 2.f*mu*s2x + mu*mu*S2c) / S1c;
                    var = fmaxf(var, 1e-4f);
                }
                const float iv = 1.f / var;
                c2s[jj][i] = iv;
                c1s[jj][i] = -2.f*mu*iv;
                ldp[jj] += __logf(var) + iv*mu*mu;
            }
        }
        #pragma unroll
        for (int i = 0; i < NSL; i++) {
            cst.c1A[i] = pack2(c1s[0][i], c1s[1][i]);
            cst.c1B[i] = pack2(c1s[2][i], c1s[3][i]);
            cst.c2A[i] = pack2(c2s[0][i], c2s[1][i]);
            cst.c2B[i] = pack2(c2s[2][i], c2s[3][i]);
        }
        u64 sld = add2(pack2(ldp[0], ldp[1]), shfl_xor64(pack2(ldp[2], ldp[3]), 2));
        float llo, lhi; unpack2(sld, llo, lhi);
        const float ld_self = llo + __shfl_xor_sync(0xffffffffu, lhi, 1);
        cst.Ck = -0.5f*(FDIM*LOG2PI + ld_self);
        for (int i = tid; i < 256; i += THREADS) s_acc[i] = 0.f;
    }

    // ---- accumulators, k-packed ----
    u64 SxA[NSL], SxB[NSL], S2xA[NSL], S2xB[NSL], S2xxA[NSL], S2xxB[NSL];
    float S1 = 0.f, S2 = 0.f;
    #pragma unroll
    for (int i = 0; i < NSL; i++) {
        SxA[i]=0; SxB[i]=0; S2xA[i]=0; S2xB[i]=0; S2xxA[i]=0; S2xxB[i]=0;
    }

    // ---- cp.async stage issue helper ----
    const float* __restrict__ gbase =
        data + ((size_t)b*NPTS + blockIdx.x*TEAMS_PER_CTA)*FDIM;
    u32 rbase;
    { u32 a; asm("{ .reg .u64 tt; cvta.to.shared.u64 tt, %1; cvt.u32.u64 %0, tt; }"
                 : "=r"(a) : "l"((const void*)&s_ring[0][0])); rbase = a; }

    auto issue_stage = [&](int js) {
        if (js < nbody) {
            const u32 sbase = rbase + (u32)(js % DEPTH)*(STAGE_F*4);
            const float* g = gbase + (size_t)js*TEAM_STRIDE*FDIM;
            {   // chunk c = tid
                const int c = tid, tp2 = c/5, q = c - 5*tp2;
                cp16(sbase + c*16, g + tp2*FDIM + q*4);
            }
            if (tid < CHUNKS - THREADS) {  // chunk c = tid + 256
                const int c = tid + THREADS, tp2 = c/5, q = c - 5*tp2;
                cp16(sbase + c*16, g + tp2*FDIM + q*4);
            }
        }
        cp_commit();   // uniform group count even when empty
    };

    // prologue: fill DEPTH-1 stages
    #pragma unroll
    for (int js = 0; js < DEPTH-1; js++) issue_stage(js);

    float* __restrict__ orp = out_resp + (size_t)b*NPTS*KC + t;
    float* __restrict__ olp = out_lp   + (size_t)b*NPTS*KC + t;

    #pragma unroll 1
    for (int j = 0; j < nbody; j++) {
        cp_wait<DEPTH-2>();
        __syncthreads();                           // all copies for stage j visible
        const float* st = &s_ring[j % DEPTH][tp*FDIM + t];
        float x[NSL];
        #pragma unroll
        for (int i = 0; i < NSL; i++) x[i] = st[4*i];
        __syncthreads();                           // reads done before slot reuse
        issue_stage(j + DEPTH - 1);

        // ---- body (identical math to R5) ----
        u64 aA = 0, aB = 0;
        #pragma unroll
        for (int i = 0; i < NSL; i++) {
            const float xf = x[i], xxf = xf*xf;
            const u64 xp  = pack2(xf,  xf);
            const u64 xxp = pack2(xxf, xxf);
            aA = fma2(cst.c2A[i], xxp, aA);
            aA = fma2(cst.c1A[i], xp,  aA);
            aB = fma2(cst.c2B[i], xxp, aB);
            aB = fma2(cst.c1B[i], xp,  aB);
        }
        u64 sA = add2(aA, shfl_xor64(aB, 2));
        float slo, shi; unpack2(sA, slo, shi);
        const float a_self = slo + __shfl_xor_sync(0xffffffffu, shi, 1);

        const float lp = fmaf(-0.5f, a_self, cst.Ck);
        const float pr = __expf(lp) + 1e-8f;
        const float p1 = __shfl_xor_sync(0xffffffffu, pr, 1);
        const u64 prA = pack2(pr, p1);
        const u64 prB = shfl_xor64(prA, 2);
        float q2, q3; unpack2(prB, q2, q3);
        const float s = (pr + p1) + (q2 + q3);
        const float rinv = __fdividef(1.f, s);
        const u64 rinv2 = pack2(rinv, rinv);
        const u64 rA = mul2(prA, rinv2), rB = mul2(prB, rinv2);
        const u64 r2A = mul2(rA, rA),    r2B = mul2(rB, rB);
        float r0, r1f; unpack2(rA, r0, r1f);
        S1 += r0; S2 += r0*r0;

        #pragma unroll
        for (int i = 0; i < NSL; i++) {
            const float xf = x[i], xxf = xf*xf;
            const u64 xp  = pack2(xf,  xf);
            const u64 xxp = pack2(xxf, xxf);
            SxA[i]   = fma2(rA,  xp,  SxA[i]);
            SxB[i]   = fma2(rB,  xp,  SxB[i]);
            S2xA[i]  = fma2(r2A, xp,  S2xA[i]);
            S2xB[i]  = fma2(r2B, xp,  S2xB[i]);
            S2xxA[i] = fma2(r2A, xxp, S2xxA[i]);
            S2xxB[i] = fma2(r2B, xxp, S2xxB[i]);
        }
        if (write_out) {
            const size_t o = (size_t)(team_g + j*TEAM_STRIDE)*KC;
            orp[o] = r0;
            olp[o] = lp;
        }
    }
    cp_wait<0>();

    // ---- cross-team warp reduce ----
    #pragma unroll
    for (int off = 4; off < 32; off <<= 1) {
        #pragma unroll
        for (int i = 0; i < NSL; i++) {
            SxA[i]   = add2(SxA[i],   shfl_xor64(SxA[i],   off));
            SxB[i]   = add2(SxB[i],   shfl_xor64(SxB[i],   off));
            S2xA[i]  = add2(S2xA[i],  shfl_xor64(S2xA[i],  off));
            S2xB[i]  = add2(S2xB[i],  shfl_xor64(S2xB[i],  off));
            S2xxA[i] = add2(S2xxA[i], shfl_xor64(S2xxA[i], off));
            S2xxB[i] = add2(S2xxB[i], shfl_xor64(S2xxB[i], off));
        }
        S1 += __shfl_xor_sync(0xffffffffu, S1, off);
        S2 += __shfl_xor_sync(0xffffffffu, S2, off);
    }

    __syncthreads();   // s_acc zeroed in prologue; ring reads done

    if (lane < 4) {    // lane == t
        #pragma unroll
        for (int i = 0; i < NSL; i++) {
            const int f = t + 4*i;
            float lo, hi;
            unpack2(SxA[i], lo, hi);
            atomicAdd(&s_acc[(t  )*FDIM + f], lo);
            atomicAdd(&s_acc[(t^1)*FDIM + f], hi);
            unpack2(SxB[i], lo, hi);
            atomicAdd(&s_acc[(t^2)*FDIM + f], lo);
            atomicAdd(&s_acc[(t^3)*FDIM + f], hi);
            unpack2(S2xA[i], lo, hi);
            atomicAdd(&s_acc[80 + (t  )*FDIM + f], lo);
            atomicAdd(&s_acc[80 + (t^1)*FDIM + f], hi);
            unpack2(S2xB[i], lo, hi);
            atomicAdd(&s_acc[80 + (t^2)*FDIM + f], lo);
            atomicAdd(&s_acc[80 + (t^3)*FDIM + f], hi);
            unpack2(S2xxA[i], lo, hi);
            atomicAdd(&s_acc[160 + (t  )*FDIM + f], lo);
            atomicAdd(&s_acc[160 + (t^1)*FDIM + f], hi);
            unpack2(S2xxB[i], lo, hi);
            atomicAdd(&s_acc[160 + (t^2)*FDIM + f], lo);
            atomicAdd(&s_acc[160 + (t^3)*FDIM + f], hi);
        }
        atomicAdd(&s_acc[240 + t], S1);
        atomicAdd(&s_acc[244 + t], S2);
    }
    __syncthreads();
    for (int i = tid; i < 248; i += THREADS)
        atomicAdd(&g_sums[it][b][i], s_acc[i]);
}

// ---------------------------------------------------------------------------
__global__ void gmm_final(float* __restrict__ out_m,
                          float* __restrict__ out_cov,
                          float* __restrict__ out_prior)
{
    const int b = blockIdx.x;
    const int k = threadIdx.x >> 5;
    const int lane = threadIdx.x & 31;
    const float* s = g_sums[4][b];

    const float S1 = s[240 + k];
    const float S2 = s[244 + k];
    float mu = 0.f, var = 1.f;
    if (lane < FDIM) {
        const float sx   = s[        k*FDIM + lane];
        const float s2x  = s[ 80 +   k*FDIM + lane];
        const float s2xx = s[160 +   k*FDIM + lane];
        mu  = sx / S1;
        var = (s2xx - 2.f*mu*s2x + mu*mu*S2) / S1;
        var = fmaxf(var, 1e-4f);
        out_m[(b*KC + k)*FDIM + lane] = mu;
    }
    if (lane == 0) out_prior[b*KC + k] = S1;
    #pragma unroll
    for (int i = 0; i < FDIM; i++) {
        const float vi = __shfl_sync(0xffffffffu, var, i);
        if (lane < FDIM)
            out_cov[(((size_t)(b*KC + k))*FDIM + i)*FDIM + lane] =
                (lane == i) ? vi : 0.f;
    }

    __syncthreads();
    for (int itt = 0; itt < 5; itt++)
        for (int i = threadIdx.x; i < 256; i += blockDim.x)
            g_sums[itt][b][i] = 0.f;
}

// ---------------------------------------------------------------------------
extern "C" void kernel_launch(void* const* d_in, const int* in_sizes, int n_in,
                              void* d_out, int out_size)
{
    (void)in_sizes; (void)n_in; (void)out_size;
    const float* data  = (const float*)d_in[0];
    const float* means = (const float*)d_in[1];
    const float* cov   = (const float*)d_in[2];
    float* out = (float*)d_out;

    float* out_resp  = out + RESP_OFF;
    float* out_lp    = out + LP_OFF;
    float* out_m     = out + M_OFF;
    float* out_cov   = out + COV_OFF;
    float* out_prior = out + PRIOR_OFF;

    for (int it = 0; it < 5; it++)
        gmm_accum<<<dim3(CTAS_PER_B, BB), THREADS>>>(
            data, means, cov, out_resp, out_lp, it, (it == 4) ? 1 : 0);
    gmm_final<<<BB, 128>>>(out_m, out_cov, out_prior);
}